// round 14
// baseline (speedup 1.0000x reference)
#include <cuda_runtime.h>
#include <math.h>

#define H 2048
#define N 16384
#define D 1024
#define EPSV 1e-8f
#define DIMSZ (5 + 3*D)   // 3077
#define UB 512            // fused shift+update blocks
#define RPB (N / UB)      // 32 rows per fused block
#define RB (N / 8)        // gate/sim blocks: 8 warps x 1 row = 2048 blocks

// ---- scratch (__device__ globals; no allocs allowed) ----
__device__ float g_dim5[5];          // beta, gamma, shift logits
__device__ float g_k[D];
__device__ float g_erase[D];
__device__ float g_add[D];
__device__ float g_s[N];             // exp(beta*sim)  (no max-sub; bounded)
__device__ float g_gate[N];
__device__ float g_sp[RB];           // per-sim-block exp partial sums
__device__ float g_pp[UB];           // per-fused-block pow-sum partials
__device__ unsigned g_arrive;        // monotonic grid-barrier ticket counter

__device__ __forceinline__ float warp_sum(float v) {
#pragma unroll
    for (int o = 16; o; o >>= 1) v += __shfl_xor_sync(0xffffffffu, v, o);
    return v;
}
__device__ __forceinline__ float dot4(float4 a, float4 b) {
    return a.x * b.x + a.y * b.y + a.z * b.z + a.w * b.w;
}

// ---------------------------------------------------------------------------
// dim_out = W_dim @ hidden + b_dim, warp-per-row (8 warps/block).
// First 4 blocks zero out[0:D]. <<<(DIMSZ+7)/8, 256>>>  [stream 0]
// ---------------------------------------------------------------------------
__global__ void __launch_bounds__(256) k_dim(const float* __restrict__ W,
                                             const float* __restrict__ h,
                                             const float* __restrict__ b,
                                             float* __restrict__ out) {
    __shared__ float4 sh[H / 4];     // 8 KB
    int t = threadIdx.x;
    {
        const float4* h4 = reinterpret_cast<const float4*>(h);
        sh[t] = h4[t];
        sh[t + 256] = h4[t + 256];
    }
    if (blockIdx.x < 4) out[blockIdx.x * 256 + t] = 0.f;   // memory_read init
    __syncthreads();

    int warp = t >> 5, lane = t & 31;
    int row = blockIdx.x * 8 + warp;
    if (row >= DIMSZ) return;

    const float4* w4 = reinterpret_cast<const float4*>(W + (size_t)row * H);
    float s = 0.f;
#pragma unroll
    for (int c = 0; c < 2; c++) {
        float4 wv[8];
#pragma unroll
        for (int u = 0; u < 8; u++) wv[u] = __ldcs(w4 + lane + 32 * (8 * c + u));
#pragma unroll
        for (int u = 0; u < 8; u++) s += dot4(wv[u], sh[lane + 32 * (8 * c + u)]);
    }
    s = warp_sum(s);
    if (lane == 0) {
        float v = s + b[row];
        if (row < 5)              g_dim5[row] = v;
        else if (row < 5 + D)     g_k[row - 5] = v;
        else if (row < 5 + 2*D)   g_erase[row - 5 - D] = v;
        else                      g_add[row - 5 - 2*D] = v;
    }
}

// ---------------------------------------------------------------------------
// Gate GEMV (INDEPENDENT of k_dim): g_gate = sigmoid(Wg @ h + bg).
// Warp-per-row, h in smem, Wg streamed 8-deep. <<<RB, 256>>>  [stream 1]
// ---------------------------------------------------------------------------
__global__ void __launch_bounds__(256) k_gate(const float* __restrict__ Wg,
                                              const float* __restrict__ h,
                                              const float* __restrict__ bg) {
    __shared__ float4 sh[H / 4];     // 8 KB
    int t = threadIdx.x;
    {
        const float4* h4 = reinterpret_cast<const float4*>(h);
        sh[t] = h4[t];
        sh[t + 256] = h4[t + 256];
    }
    __syncthreads();

    int warp = t >> 5, lane = t & 31;
    int row = blockIdx.x * 8 + warp;
    const float4* w4 = reinterpret_cast<const float4*>(Wg + (size_t)row * H);
    float d3 = 0.f;
#pragma unroll
    for (int c = 0; c < 2; c++) {
        float4 wv[8];
#pragma unroll
        for (int u = 0; u < 8; u++) wv[u] = __ldcs(w4 + lane + 32 * (8 * c + u));
#pragma unroll
        for (int u = 0; u < 8; u++) d3 += dot4(wv[u], sh[lane + 32 * (8 * c + u)]);
    }
    d3 = warp_sum(d3);
    if (lane == 0)
        g_gate[row] = 1.f / (1.f + expf(-(d3 + bg[row])));
}

// ---------------------------------------------------------------------------
// Similarity pass (depends on k_dim): dot(mem_i,k), ||mem_i||^2, ||k||^2
// -> g_s[i] = exp(beta*cos_sim), per-block partials g_sp.
// Warp-per-row, k in smem, mem 8-deep batched. <<<RB, 256>>>  [stream 0]
// ---------------------------------------------------------------------------
__global__ void __launch_bounds__(256) k_sim(const float* __restrict__ mem) {
    __shared__ float4 sk[D / 4];     // 4 KB
    __shared__ float sexp[8];
    int t = threadIdx.x;
    sk[t] = reinterpret_cast<const float4*>(g_k)[t];
    __syncthreads();

    int warp = t >> 5, lane = t & 31;
    int row = blockIdx.x * 8 + warp;

    const float4* m4 = reinterpret_cast<const float4*>(mem + (size_t)row * D);
    float4 mv[8];
#pragma unroll
    for (int u = 0; u < 8; u++) mv[u] = m4[lane + 32 * u];

    float d1 = 0.f, d2 = 0.f, k2 = 0.f;
#pragma unroll
    for (int u = 0; u < 8; u++) {
        float4 kk = sk[lane + 32 * u];
        d1 += dot4(mv[u], kk);
        d2 += dot4(mv[u], mv[u]);
        k2 += dot4(kk, kk);
    }
    d1 = warp_sum(d1); d2 = warp_sum(d2); k2 = warp_sum(k2);
    if (lane == 0) {
        float sim = d1 / (sqrtf(d2) * sqrtf(k2) + EPSV);
        float ev = expf(g_dim5[0] * sim);      // bounded: |beta*sim| small
        g_s[row] = ev;
        sexp[warp] = ev;
    }
    __syncthreads();
    if (t == 0) {
        float v = 0.f;
#pragma unroll
        for (int i = 0; i < 8; i++) v += sexp[i];
        g_sp[blockIdx.x] = v;                  // softmax denominator partial
    }
}

// ---------------------------------------------------------------------------
// FUSED shift + update + weight output + memory_read (grid barrier between
// phases). Update loop: proven LDG 8-deep batched form (R9; 26.7us, 42% DRAM).
// <<<UB, 256>>>
// ---------------------------------------------------------------------------
__device__ __forceinline__ float wg_at(int j, float inv_sum,
                                       const float* __restrict__ lw) {
    j &= (N - 1);
    float g = g_gate[j];
    return g * g_s[j] * inv_sum + (1.f - g) * lw[j];
}

__global__ void __launch_bounds__(256, 4) k_fused(const float* __restrict__ mem,
                                                  const float* __restrict__ lw,
                                                  float* __restrict__ out) {
    int t = threadIdx.x;
    int warp = t >> 5, lane = t & 31;
    __shared__ float red[8];
    __shared__ float bc;
    __shared__ float w_s[RPB];

    // phase 0: softmax denominator from 2048 partials
    float s = 0.f;
#pragma unroll
    for (int u = 0; u < RB / 256; u++) s += g_sp[t + 256 * u];
    s = warp_sum(s);
    if (lane == 0) red[warp] = s;
    __syncthreads();
    if (t == 0) {
        float v = 0.f;
#pragma unroll
        for (int i = 0; i < 8; i++) v += red[i];
        bc = 1.f / v;
    }
    __syncthreads();
    float inv_sum = bc;

    // phase 1: shift conv + pow for this block's 32 rows (warp 0 only)
    int base = blockIdx.x * RPB;
    if (t < RPB) {
        float a0 = g_dim5[2], a1 = g_dim5[3], a2 = g_dim5[4];
        float mm = fmaxf(a0, fmaxf(a1, a2));
        float e0 = expf(a0 - mm), e1 = expf(a1 - mm), e2 = expf(a2 - mm);
        float inv3 = 1.f / (e0 + e1 + e2);
        float gamma = g_dim5[1];
        int i = base + t;
        float wt = e0 * inv3 * wg_at(i - 1, inv_sum, lw)
                 + e1 * inv3 * wg_at(i,     inv_sum, lw)
                 + e2 * inv3 * wg_at(i + 1, inv_sum, lw);
        float wp = powf(wt, gamma);
        w_s[t] = wp;
        float p = warp_sum(wp);
        if (t == 0) g_pp[blockIdx.x] = p;     // pow-sum partial
    }
    __syncthreads();

    // grid sync: monotonic ticket counter (exactly UB arrivals per launch)
    if (t == 0) {
        __threadfence();
        unsigned ticket = atomicAdd(&g_arrive, 1u);
        unsigned target = (ticket / UB + 1u) * UB;
        while (atomicAdd(&g_arrive, 0u) < target) { }
    }
    __syncthreads();
    __threadfence();

    // phase 2: global pow-sum -> inv; weight out; memory update
    float v2 = g_pp[t] + g_pp[t + 256];
    v2 = warp_sum(v2);
    if (lane == 0) red[warp] = v2;
    __syncthreads();
    if (t == 0) {
        float v = 0.f;
#pragma unroll
        for (int i = 0; i < 8; i++) v += red[i];
        bc = 1.f / v;
    }
    __syncthreads();
    float inv = bc;

    if (t < RPB) out[D + base + t] = w_s[t] * inv;   // weight output

    float4* newm = reinterpret_cast<float4*>(out + D + N);
    const float4* m4 = reinterpret_cast<const float4*>(mem);
    float4 e4 = reinterpret_cast<const float4*>(g_erase)[t];
    float4 a4 = reinterpret_cast<const float4*>(g_add)[t];
    float4 acc = make_float4(0.f, 0.f, 0.f, 0.f);

#pragma unroll
    for (int r0 = 0; r0 < RPB; r0 += 8) {
        float4 m[8];
#pragma unroll
        for (int u = 0; u < 8; u++)
            m[u] = m4[(size_t)(base + r0 + u) * 256 + t];
#pragma unroll
        for (int u = 0; u < 8; u++) {
            float w = w_s[r0 + u] * inv;
            acc.x += w * m[u].x; acc.y += w * m[u].y;
            acc.z += w * m[u].z; acc.w += w * m[u].w;
            float4 nm;
            nm.x = m[u].x * (1.f - w * e4.x) + w * a4.x;
            nm.y = m[u].y * (1.f - w * e4.y) + w * a4.y;
            nm.z = m[u].z * (1.f - w * e4.z) + w * a4.z;
            nm.w = m[u].w * (1.f - w * e4.w) + w * a4.w;
            newm[(size_t)(base + r0 + u) * 256 + t] = nm;
        }
    }
    // memory_read: direct reduce into pre-zeroed out[0:D]
    atomicAdd(&out[4 * t + 0], acc.x);
    atomicAdd(&out[4 * t + 1], acc.y);
    atomicAdd(&out[4 * t + 2], acc.z);
    atomicAdd(&out[4 * t + 3], acc.w);
}

// ---------------------------------------------------------------------------
// DAG:   [k_dim -> k_sim]  (stream 0)
//        [k_gate]          (stream 1, forked/joined via events)
//        -> k_fused        (stream 0)
// Streams/events are host resources (no device memory), lazily created once.
// ---------------------------------------------------------------------------
extern "C" void kernel_launch(void* const* d_in, const int* in_sizes, int n_in,
                              void* d_out, int out_size) {
    const float* hidden = (const float*)d_in[0];
    const float* lw     = (const float*)d_in[1];
    const float* mem    = (const float*)d_in[2];
    const float* Wd     = (const float*)d_in[3];
    const float* bd     = (const float*)d_in[4];
    const float* Wg     = (const float*)d_in[5];
    const float* bg     = (const float*)d_in[6];
    float* out = (float*)d_out;

    static cudaStream_t s1 = nullptr;
    static cudaEvent_t ev_fork = nullptr, ev_join = nullptr;
    if (s1 == nullptr) {
        cudaStreamCreateWithFlags(&s1, cudaStreamNonBlocking);
        cudaEventCreateWithFlags(&ev_fork, cudaEventDisableTiming);
        cudaEventCreateWithFlags(&ev_join, cudaEventDisableTiming);
    }

    // fork: gate GEMV (independent) on s1
    cudaEventRecord(ev_fork, 0);
    cudaStreamWaitEvent(s1, ev_fork, 0);
    k_gate<<<RB, 256, 0, s1>>>(Wg, hidden, bg);
    cudaEventRecord(ev_join, s1);

    // main branch: dim -> sim
    k_dim<<<(DIMSZ + 7) / 8, 256>>>(Wd, hidden, bd, out);
    k_sim<<<RB, 256>>>(mem);

    // join, then fused epilogue
    cudaStreamWaitEvent((cudaStream_t)0, ev_join, 0);
    k_fused<<<UB, 256>>>(mem, lw, out);
}